// round 2
// baseline (speedup 1.0000x reference)
#include <cuda_runtime.h>
#include <math.h>

// Problem constants
#define NPTS   12288      // 96*128 points
#define KDIM   512        // channels
#define NTILES 96         // 12288 / 128
#define BM     128
#define BN     128
#define BK     16
#define TILE_LD 129       // padded leading dim for smem tile (conflict-free scans)

// ---------------- scratch (device globals: allocation-guard safe) ------------
__device__ float g_invA[NPTS];
__device__ float g_invB[NPTS];
// per-(row, colTile) top-2 partials and per-(col, rowTile) top-2 partials
__device__ float g_rowPV[NPTS * NTILES * 2];
__device__ int   g_rowPI[NPTS * NTILES * 2];
__device__ float g_colPV[NPTS * NTILES * 2];
__device__ int   g_colPI[NPTS * NTILES * 2];
// merged results
__device__ int   g_nn12[NPTS];
__device__ float g_s12_0[NPTS];
__device__ float g_s12_1[NPTS];
__device__ int   g_nn21[NPTS];
__device__ float g_r21[NPTS];

// ---------------- kernel 1: inverse L2 norms ---------------------------------
__global__ void invnorm_kernel(const float* __restrict__ A, const float* __restrict__ B) {
    int p = blockIdx.x * blockDim.x + threadIdx.x;
    if (p >= NPTS) return;
    float sa = 0.f, sb = 0.f;
#pragma unroll 8
    for (int c = 0; c < KDIM; c++) {
        float a = A[c * NPTS + p];
        float b = B[c * NPTS + p];
        sa = fmaf(a, a, sa);
        sb = fmaf(b, b, sb);
    }
    g_invA[p] = 1.0f / sqrtf(sa);
    g_invB[p] = 1.0f / sqrtf(sb);
}

// ---------------- kernel 2: fused GEMM + per-tile top-2 (rows & cols) --------
// C[bm0+r, bn0+c] = sum_k A[k, bm0+r] * B[k, bn0+c] * invA * invB
// Layout: A, B are [KDIM][NPTS] row-major (channel-major) -> point dim contiguous.
__global__ void __launch_bounds__(256, 2)
gemm_top2_kernel(const float* __restrict__ A, const float* __restrict__ B) {
    extern __shared__ float smem[];
    float* As   = smem;                 // [BK][BM] during K loop
    float* Bs   = smem + BK * BM;       // [BK][BN]
    float* tile = smem;                 // [BM][TILE_LD] after K loop (aliases As/Bs)

    const int tid = threadIdx.x;
    const int tx  = tid & 15;           // 0..15 -> col micro-tile
    const int ty  = tid >> 4;           // 0..15 -> row micro-tile
    const int bj  = blockIdx.x;         // col tile
    const int bi  = blockIdx.y;         // row tile
    const int bm0 = bi * BM;
    const int bn0 = bj * BN;

    float acc[8][8];
#pragma unroll
    for (int i = 0; i < 8; i++)
#pragma unroll
        for (int j = 0; j < 8; j++) acc[i][j] = 0.f;

    for (int k0 = 0; k0 < KDIM; k0 += BK) {
        // cooperative load: 2048 floats per operand = 512 float4, 2 per thread
#pragma unroll
        for (int v = 0; v < 2; v++) {
            int t  = tid + v * 256;     // 0..511
            int kk = t >> 5;            // 0..15
            int mm = (t & 31) << 2;     // 0..124
            int ga = (k0 + kk) * NPTS;
            float4 av = *(const float4*)&A[ga + bm0 + mm];
            float4 bv = *(const float4*)&B[ga + bn0 + mm];
            *(float4*)&As[kk * BM + mm] = av;
            *(float4*)&Bs[kk * BN + mm] = bv;
        }
        __syncthreads();
#pragma unroll
        for (int kk = 0; kk < BK; kk++) {
            float a[8], b[8];
            *(float4*)&a[0] = *(const float4*)&As[kk * BM + ty * 8];
            *(float4*)&a[4] = *(const float4*)&As[kk * BM + ty * 8 + 4];
            *(float4*)&b[0] = *(const float4*)&Bs[kk * BN + tx * 8];
            *(float4*)&b[4] = *(const float4*)&Bs[kk * BN + tx * 8 + 4];
#pragma unroll
            for (int i = 0; i < 8; i++)
#pragma unroll
                for (int j = 0; j < 8; j++)
                    acc[i][j] = fmaf(a[i], b[j], acc[i][j]);
        }
        __syncthreads();
    }

    // epilogue: scale by inverse norms, stage full tile in smem
    float ia[8], ib[8];
#pragma unroll
    for (int i = 0; i < 8; i++) {
        ia[i] = g_invA[bm0 + ty * 8 + i];
        ib[i] = g_invB[bn0 + tx * 8 + i];
    }
#pragma unroll
    for (int i = 0; i < 8; i++)
#pragma unroll
        for (int j = 0; j < 8; j++)
            tile[(ty * 8 + i) * TILE_LD + tx * 8 + j] = acc[i][j] * ia[i] * ib[j];
    __syncthreads();

    // top-2 scans: threads 0..127 do rows, 128..255 do columns (conflict-free via pad)
    if (tid < 128) {
        int r = tid;
        float v0 = -2.f, v1 = -2.f;
        int   i0 = 0,    i1 = 0;
#pragma unroll 4
        for (int j = 0; j < BN; j++) {
            float v = tile[r * TILE_LD + j];
            if (v > v0) { v1 = v0; i1 = i0; v0 = v; i0 = bn0 + j; }
            else if (v > v1) { v1 = v; i1 = bn0 + j; }
        }
        int base = ((bm0 + r) * NTILES + bj) * 2;
        g_rowPV[base] = v0; g_rowPV[base + 1] = v1;
        g_rowPI[base] = i0; g_rowPI[base + 1] = i1;
    } else {
        int c = tid - 128;
        float v0 = -2.f, v1 = -2.f;
        int   i0 = 0,    i1 = 0;
#pragma unroll 4
        for (int r = 0; r < BM; r++) {
            float v = tile[r * TILE_LD + c];
            if (v > v0) { v1 = v0; i1 = i0; v0 = v; i0 = bm0 + r; }
            else if (v > v1) { v1 = v; i1 = bm0 + r; }
        }
        int base = ((bn0 + c) * NTILES + bi) * 2;
        g_colPV[base] = v0; g_colPV[base + 1] = v1;
        g_colPI[base] = i0; g_colPI[base + 1] = i1;
    }
}

// ---------------- kernel 3: merge partials -----------------------------------
__global__ void merge_kernel() {
    int t = blockIdx.x * blockDim.x + threadIdx.x;
    if (t < NPTS) {
        int r = t;
        float v0 = -2.f, v1 = -2.f;
        int   i0 = 0,    i1 = 0;
        for (int tt = 0; tt < NTILES; tt++) {
            int base = (r * NTILES + tt) * 2;
            float a0 = g_rowPV[base];     int j0 = g_rowPI[base];
            float a1 = g_rowPV[base + 1]; int j1 = g_rowPI[base + 1];
            if (a0 > v0) { v1 = v0; i1 = i0; v0 = a0; i0 = j0; }
            else if (a0 > v1) { v1 = a0; i1 = j0; }
            if (a1 > v0) { v1 = v0; i1 = i0; v0 = a1; i0 = j1; }
            else if (a1 > v1) { v1 = a1; i1 = j1; }
        }
        g_nn12[r] = i0; g_s12_0[r] = v0; g_s12_1[r] = v1;
    } else if (t < 2 * NPTS) {
        int c = t - NPTS;
        float v0 = -2.f, v1 = -2.f;
        int   i0 = 0,    i1 = 0;
        for (int tt = 0; tt < NTILES; tt++) {
            int base = (c * NTILES + tt) * 2;
            float a0 = g_colPV[base];     int j0 = g_colPI[base];
            float a1 = g_colPV[base + 1]; int j1 = g_colPI[base + 1];
            if (a0 > v0) { v1 = v0; i1 = i0; v0 = a0; i0 = j0; }
            else if (a0 > v1) { v1 = a0; i1 = j0; }
            if (a1 > v0) { v1 = v0; i1 = i0; v0 = a1; i0 = j1; }
            else if (a1 > v1) { v1 = a1; i1 = j1; }
        }
        float d0 = 2.f - 2.f * v0;
        float d1 = 2.f - 2.f * v1;
        g_nn21[c] = i0;
        g_r21[c]  = d0 / (d1 + 1e-8f);
    }
}

// ---------------- kernel 4: mutual NN + ratio mask, write outputs ------------
__global__ void final_kernel(float* __restrict__ out) {
    int r = blockIdx.x * blockDim.x + threadIdx.x;
    if (r >= NPTS) return;
    int   j  = g_nn12[r];
    float s0 = g_s12_0[r];
    float s1 = g_s12_1[r];
    float ratio12 = (2.f - 2.f * s0) / ((2.f - 2.f * s1) + 1e-8f);
    bool m = (g_nn21[j] == r) && (ratio12 <= 0.95f) && (g_r21[j] <= 0.95f);
    out[r]             = m ? s0 : 0.f;      // masked_sim
    out[NPTS + r]      = (float)j;          // nn12
    out[2 * NPTS + r]  = m ? 1.f : 0.f;     // mask
}

// ---------------- launcher ----------------------------------------------------
extern "C" void kernel_launch(void* const* d_in, const int* in_sizes, int n_in,
                              void* d_out, int out_size) {
    const float* A = (const float*)d_in[0];
    const float* B = (const float*)d_in[1];
    float* out = (float*)d_out;

    const int smem_bytes = BM * TILE_LD * sizeof(float);  // 66048 B
    cudaFuncSetAttribute(gemm_top2_kernel,
                         cudaFuncAttributeMaxDynamicSharedMemorySize, smem_bytes);

    invnorm_kernel<<<(NPTS + 255) / 256, 256>>>(A, B);

    dim3 grid(NTILES, NTILES);
    gemm_top2_kernel<<<grid, 256, smem_bytes>>>(A, B);

    merge_kernel<<<(2 * NPTS + 255) / 256, 256>>>();

    final_kernel<<<(NPTS + 255) / 256, 256>>>(out);
}